// round 11
// baseline (speedup 1.0000x reference)
#include <cuda_runtime.h>
#include <math.h>

// ---------------------------------------------------------------------------
// QConv2D: 4-qubit circuit on every 2x2 patch of x(32,1,128,128).
// Z_w(patch) = P_L^T B_w P_R,  P = g_top (x) g_bot, g=(1,cos x,sin x).
// B_w (4 x 9 x 9) depends only on params; computed per-block (cheap, hidden).
// Bilinear form evaluated in Horner-factored form so only raw trig values
// (not the 9-entry Kronecker products) live in registers. 4 patches/thread
// packed into f32x2 lanes as pairs (j, j+2).
// ---------------------------------------------------------------------------

typedef unsigned long long u64;

#define FMA2(acc, a, b) \
    asm("fma.rn.f32x2 %0, %1, %2, %0;" : "+l"(acc) : "l"(a), "l"(b))
#define FMA2N(d, a, b, c) \
    asm("fma.rn.f32x2 %0, %1, %2, %3;" : "=l"(d) : "l"(a), "l"(b), "l"(c))

__device__ __forceinline__ u64 pk(float lo, float hi) {
    u64 r; asm("mov.b64 %0, {%1, %2};" : "=l"(r) : "f"(lo), "f"(hi)); return r;
}
__device__ __forceinline__ void upk(float& lo, float& hi, u64 v) {
    asm("mov.b64 {%0, %1}, %2;" : "=f"(lo), "=f"(hi) : "l"(v));
}
__device__ __forceinline__ float2 cmulf(float2 a, float2 b) {
    return make_float2(a.x * b.x - a.y * b.y, a.x * b.y + a.y * b.x);
}

// y = (cf0 + cf1*CB + cf2*SB) + CT*(cf3 + cf4*CB + cf5*SB)
//                             + ST*(cf6 + cf7*CB + cf8*SB)      [8 FMA2]
__device__ __forceinline__ u64 yrowH(const u64* cf, u64 CB, u64 SB,
                                     u64 CT, u64 ST) {
    u64 t0, t1, t2;
    FMA2N(t0, cf[1], CB, cf[0]);
    FMA2(t0, cf[2], SB);
    FMA2N(t1, cf[4], CB, cf[3]);
    FMA2(t1, cf[5], SB);
    FMA2N(t2, cf[7], CB, cf[6]);
    FMA2(t2, cf[8], SB);
    FMA2(t0, CT, t1);
    FMA2(t0, ST, t2);
    return t0;
}

// Block: 128 threads = 4 rows x 32 col-groups (4 patches each).
// Grid: (32 row-groups, 32 batches) = 1024 blocks; 7 CTAs/SM -> one wave.
__global__ __launch_bounds__(128, 7) void qconv_fused(
    const float* __restrict__ x, const float* __restrict__ params,
    float* __restrict__ out)
{
    __shared__ float2 shM[2][4][2][2];
    __shared__ float2 shG[2][16][16];
    __shared__ float2 shU[16][16];
    __shared__ float  shA[4][16][16];
    // B coefficients, duplicated {c,c}; row (w,a) = 10 u64 slots (80B):
    // slot b (0..8) = B_w[a][b] in b = 3*k1+k3 order, slot 9 = pad.
    __shared__ __align__(16) u64 sBd[4 * 9 * 10];

    const int tid = threadIdx.x;

    // ================= per-block precompute of B =================
    if (tid < 8) {  // single-qubit mats m = RZ(tz)*RX(tx)
        int l = tid >> 2, w = tid & 3;
        float tx = params[(l * 4 + w) * 2 + 0];
        float tz = params[(l * 4 + w) * 2 + 1];
        float s, c, sz, cz;
        sincosf(0.5f * tx, &s, &c);
        sincosf(0.5f * tz, &sz, &cz);
        shM[l][w][0][0] = make_float2(cz * c, -sz * c);
        shM[l][w][0][1] = make_float2(-s * sz, -s * cz);
        shM[l][w][1][0] = make_float2(s * sz, -s * cz);
        shM[l][w][1][1] = make_float2(c * cz, c * sz);
    }
    __syncthreads();

    // G_l = CNOTperm * (m0 (x) m1 (x) m2 (x) m3)
    for (int t = tid; t < 256; t += 128) {
        int i = t >> 4, j = t & 15;
        int r = i;
        if (r & 1) r ^= 2;
        if (r & 2) r ^= 4;
        if (r & 4) r ^= 8;
#pragma unroll
        for (int l = 0; l < 2; l++) {
            float2 g = shM[l][0][(r >> 3) & 1][(j >> 3) & 1];
            g = cmulf(g, shM[l][1][(r >> 2) & 1][(j >> 2) & 1]);
            g = cmulf(g, shM[l][2][(r >> 1) & 1][(j >> 1) & 1]);
            g = cmulf(g, shM[l][3][r & 1][j & 1]);
            shG[l][i][j] = g;
        }
    }
    __syncthreads();

    // U = G1 * G0
    for (int t = tid; t < 256; t += 128) {
        int i = t >> 4, j = t & 15;
        float2 acc = make_float2(0.f, 0.f);
#pragma unroll
        for (int m = 0; m < 16; m++) {
            float2 a = shG[1][i][m], bb = shG[0][m][j];
            acc.x += a.x * bb.x - a.y * bb.y;
            acc.y += a.x * bb.y + a.y * bb.x;
        }
        shU[i][j] = acc;
    }
    __syncthreads();

    // A_w[i][j] = Re( i^{popc(i)-popc(j)} sum_k d_w(k) conj(U[k,i]) U[k,j] )
    for (int t = tid; t < 256; t += 128) {
        int i = t >> 4, j = t & 15;
        float ar[4] = {0, 0, 0, 0}, ai[4] = {0, 0, 0, 0};
#pragma unroll
        for (int k = 0; k < 16; k++) {
            float2 ui = shU[k][i], uj = shU[k][j];
            float cr = ui.x * uj.x + ui.y * uj.y;
            float ci = ui.x * uj.y - ui.y * uj.x;
#pragma unroll
            for (int w = 0; w < 4; w++) {
                float sgn = (k & (1 << (3 - w))) ? -1.f : 1.f;
                ar[w] += sgn * cr;
                ai[w] += sgn * ci;
            }
        }
        int ph = (__popc(i) - __popc(j)) & 3;
#pragma unroll
        for (int w = 0; w < 4; w++) {
            float re;
            if (ph == 0)      re =  ar[w];
            else if (ph == 1) re = -ai[w];
            else if (ph == 2) re = -ar[w];
            else              re =  ai[w];
            shA[w][i][j] = re;
        }
    }
    __syncthreads();

    // half-angle -> full-angle basis, write duplicated {v,v}
    for (int idx = tid; idx < 324; idx += 128) {
        int w = idx / 81, r = idx % 81;
        int a = r / 9, bq = r % 9;
        int k0 = a / 3, k2 = a % 3, k1 = bq / 3, k3 = bq % 3;
        int xmask = ((k0 == 2) ? 8 : 0) | ((k1 == 2) ? 4 : 0) |
                    ((k2 == 2) ? 2 : 0) | ((k3 == 2) ? 1 : 0);
        int smask = ((k0 == 1) ? 8 : 0) | ((k1 == 1) ? 4 : 0) |
                    ((k2 == 1) ? 2 : 0) | ((k3 == 1) ? 1 : 0);
        float sum = 0.f;
#pragma unroll
        for (int i = 0; i < 16; i++) {
            float sgn = (__popc(i & smask) & 1) ? -1.f : 1.f;
            sum += sgn * shA[w][i][i ^ xmask];
        }
        float v = sum * (1.f / 16.f);
        unsigned ub = __float_as_uint(v);
        sBd[(w * 9 + a) * 10 + bq] = ((u64)ub << 32) | ub;
    }
    __syncthreads();

    // ================= main compute: 4 patches per thread =================
    const int b  = blockIdx.y;
    const int ti = tid >> 5;               // 0..3
    const int tj = tid & 31;               // 0..31
    const int i  = blockIdx.x * 4 + ti;    // output row (127 invalid)
    const int j0 = tj * 4;
    const int i0 = (i < 126) ? i : 126;

    const float* px = x + b * 16384 + i0 * 128 + j0;

    // trig for 5 columns x 2 rows
    float tv[5], bv[5];
    {
        float4 t4 = *(const float4*)px;
        float4 b4 = *(const float4*)(px + 128);
        tv[0]=t4.x; tv[1]=t4.y; tv[2]=t4.z; tv[3]=t4.w;
        bv[0]=b4.x; bv[1]=b4.y; bv[2]=b4.z; bv[3]=b4.w;
        int e = (j0 + 4 <= 127) ? 4 : 3;
        tv[4] = px[e];
        bv[4] = px[128 + e];
    }
    float ct[5], st[5], cb[5], sb[5];
#pragma unroll
    for (int c = 0; c < 5; c++) {
        __sincosf(tv[c], &st[c], &ct[c]);
        __sincosf(bv[c], &sb[c], &cb[c]);
    }

    // Packed raw-trig for column pairs q: {q, q+2}
    u64 CB[3], SB[3], CT[3], ST[3];
#pragma unroll
    for (int q = 0; q < 3; q++) {
        CB[q] = pk(cb[q], cb[q + 2]);
        SB[q] = pk(sb[q], sb[q + 2]);
        CT[q] = pk(ct[q], ct[q + 2]);
        ST[q] = pk(st[q], st[q + 2]);
    }

    const bool rowok = (i < 127);
    const bool last = (j0 + 3 >= 127);     // only patch j0+3 can be invalid
    float* ob = out + ((size_t)(b * 4) * 127 + i) * 127 + j0;

#pragma unroll 1
    for (int w = 0; w < 4; w++) {
        const u64* wp = sBd + w * 90;
        // chain0: patches (j0, j0+2): left pair 0, right pair 1
        // chain1: patches (j0+1, j0+3): left pair 1, right pair 2
        u64 sA[3], sC[3];
#pragma unroll
        for (int k0 = 0; k0 < 3; k0++) {
#pragma unroll
            for (int k2 = 0; k2 < 3; k2++) {
                const u64* rp = wp + (k0 * 3 + k2) * 10;
                u64 cf[9];
                *(ulonglong2*)(cf + 0) = *(const ulonglong2*)(rp + 0);
                *(ulonglong2*)(cf + 2) = *(const ulonglong2*)(rp + 2);
                *(ulonglong2*)(cf + 4) = *(const ulonglong2*)(rp + 4);
                *(ulonglong2*)(cf + 6) = *(const ulonglong2*)(rp + 6);
                cf[8] = rp[8];
                u64 y0 = yrowH(cf, CB[1], SB[1], CT[1], ST[1]);
                u64 y1 = yrowH(cf, CB[2], SB[2], CT[2], ST[2]);
                if (k2 == 0) { sA[k0] = y0; sC[k0] = y1; }
                else if (k2 == 1) { FMA2(sA[k0], CB[0], y0); FMA2(sC[k0], CB[1], y1); }
                else              { FMA2(sA[k0], SB[0], y0); FMA2(sC[k0], SB[1], y1); }
            }
        }
        u64 z02 = sA[0], z13 = sC[0];
        FMA2(z02, CT[0], sA[1]);
        FMA2(z02, ST[0], sA[2]);
        FMA2(z13, CT[1], sC[1]);
        FMA2(z13, ST[1], sC[2]);

        if (rowok) {
            float* orow = ob + (size_t)w * (127 * 127);
            float lo, hi;
            upk(lo, hi, z02); orow[0] = lo; orow[2] = hi;
            upk(lo, hi, z13); orow[1] = lo;
            if (!last) orow[3] = hi;
        }
    }
}

// ------------------------------- launcher ----------------------------------
extern "C" void kernel_launch(void* const* d_in, const int* in_sizes, int n_in,
                              void* d_out, int out_size) {
    const float* x      = (const float*)d_in[0];
    const float* params = (const float*)d_in[1];
    if (n_in >= 2 && in_sizes[0] == 16) {  // robustness to input order
        params = (const float*)d_in[0];
        x      = (const float*)d_in[1];
    }
    float* out = (float*)d_out;

    dim3 grid(32, 32);   // 32 row-groups (4 rows) x 32 batches = 1024 blocks
    qconv_fused<<<grid, 128>>>(x, params, out);
}

// round 13
// speedup vs baseline: 1.1196x; 1.1196x over previous
#include <cuda_runtime.h>
#include <math.h>

// ---------------------------------------------------------------------------
// QConv2D: 4-qubit circuit on every 2x2 patch of x(32,1,128,128).
// Z_w(patch) = P_L^T B_w P_R,  P = g_top (x) g_bot, g=(1,cos x,sin x).
// B_w (4 x 9 x 9) depends only on params; computed ONCE by a tiny kernel
// (parallel: G-matrix Kronecker build + 16x16 complex matmul), stored
// duplicated {c,c} in global. Main kernel evaluates the bilinear form in
// Horner-factored form with packed f32x2 FMA, 4 patches/thread.
// ---------------------------------------------------------------------------

typedef unsigned long long u64;

#define FMA2(acc, a, b) \
    asm("fma.rn.f32x2 %0, %1, %2, %0;" : "+l"(acc) : "l"(a), "l"(b))
#define FMA2N(d, a, b, c) \
    asm("fma.rn.f32x2 %0, %1, %2, %3;" : "=l"(d) : "l"(a), "l"(b), "l"(c))

__device__ __forceinline__ u64 pk(float lo, float hi) {
    u64 r; asm("mov.b64 %0, {%1, %2};" : "=l"(r) : "f"(lo), "f"(hi)); return r;
}
__device__ __forceinline__ void upk(float& lo, float& hi, u64 v) {
    asm("mov.b64 {%0, %1}, %2;" : "=f"(lo), "=f"(hi) : "l"(v));
}
__device__ __forceinline__ float2 cmulf(float2 a, float2 b) {
    return make_float2(a.x * b.x - a.y * b.y, a.x * b.y + a.y * b.x);
}

// B coefficients, duplicated {c,c}; row (w,a) = 10 u64 slots (80B):
// slots 0..8 = B_w[a][b] (b = 3*k1+k3), slot 9 = pad.
__device__ u64 d_Bg[4 * 9 * 10];

// ---------------------------- precompute kernel ----------------------------
__global__ void qconv_precompute(const float* __restrict__ params) {
    __shared__ float2 shM[2][4][2][2];
    __shared__ float2 shG[2][16][16];
    __shared__ float2 shU[16][16];
    __shared__ float  shA[4][16][16];
    const int tid = threadIdx.x;

    if (tid < 8) {  // single-qubit mats m = RZ(tz)*RX(tx)
        int l = tid >> 2, w = tid & 3;
        float tx = params[(l * 4 + w) * 2 + 0];
        float tz = params[(l * 4 + w) * 2 + 1];
        float s, c, sz, cz;
        sincosf(0.5f * tx, &s, &c);
        sincosf(0.5f * tz, &sz, &cz);
        shM[l][w][0][0] = make_float2(cz * c, -sz * c);
        shM[l][w][0][1] = make_float2(-s * sz, -s * cz);
        shM[l][w][1][0] = make_float2(s * sz, -s * cz);
        shM[l][w][1][1] = make_float2(c * cz, c * sz);
    }
    __syncthreads();

    {   // G_l = CNOTperm * (m0 (x) m1 (x) m2 (x) m3)
        int i = tid >> 4, j = tid & 15;
        int r = i;
        if (r & 1) r ^= 2;
        if (r & 2) r ^= 4;
        if (r & 4) r ^= 8;
#pragma unroll
        for (int l = 0; l < 2; l++) {
            float2 g = shM[l][0][(r >> 3) & 1][(j >> 3) & 1];
            g = cmulf(g, shM[l][1][(r >> 2) & 1][(j >> 2) & 1]);
            g = cmulf(g, shM[l][2][(r >> 1) & 1][(j >> 1) & 1]);
            g = cmulf(g, shM[l][3][r & 1][j & 1]);
            shG[l][i][j] = g;
        }
    }
    __syncthreads();

    {   // U = G1 * G0
        int i = tid >> 4, j = tid & 15;
        float2 acc = make_float2(0.f, 0.f);
#pragma unroll
        for (int m = 0; m < 16; m++) {
            float2 a = shG[1][i][m], bb = shG[0][m][j];
            acc.x += a.x * bb.x - a.y * bb.y;
            acc.y += a.x * bb.y + a.y * bb.x;
        }
        shU[i][j] = acc;
    }
    __syncthreads();

    {   // A_w[i][j] = Re( i^{popc(i)-popc(j)} sum_k d_w(k) conj(U[k,i]) U[k,j] )
        int i = tid >> 4, j = tid & 15;
        float ar[4] = {0, 0, 0, 0}, ai[4] = {0, 0, 0, 0};
#pragma unroll
        for (int k = 0; k < 16; k++) {
            float2 ui = shU[k][i], uj = shU[k][j];
            float cr = ui.x * uj.x + ui.y * uj.y;
            float ci = ui.x * uj.y - ui.y * uj.x;
#pragma unroll
            for (int w = 0; w < 4; w++) {
                float sgn = (k & (1 << (3 - w))) ? -1.f : 1.f;
                ar[w] += sgn * cr;
                ai[w] += sgn * ci;
            }
        }
        int ph = (__popc(i) - __popc(j)) & 3;
#pragma unroll
        for (int w = 0; w < 4; w++) {
            float re;
            if (ph == 0)      re =  ar[w];
            else if (ph == 1) re = -ai[w];
            else if (ph == 2) re = -ar[w];
            else              re =  ai[w];
            shA[w][i][j] = re;
        }
    }
    __syncthreads();

    // half-angle -> full-angle basis, write duplicated {v,v}
    for (int idx = tid; idx < 324; idx += 256) {
        int w = idx / 81, r = idx % 81;
        int a = r / 9, bq = r % 9;
        int k0 = a / 3, k2 = a % 3, k1 = bq / 3, k3 = bq % 3;
        int xmask = ((k0 == 2) ? 8 : 0) | ((k1 == 2) ? 4 : 0) |
                    ((k2 == 2) ? 2 : 0) | ((k3 == 2) ? 1 : 0);
        int smask = ((k0 == 1) ? 8 : 0) | ((k1 == 1) ? 4 : 0) |
                    ((k2 == 1) ? 2 : 0) | ((k3 == 1) ? 1 : 0);
        float sum = 0.f;
#pragma unroll
        for (int i = 0; i < 16; i++) {
            float sgn = (__popc(i & smask) & 1) ? -1.f : 1.f;
            sum += sgn * shA[w][i][i ^ xmask];
        }
        float v = sum * (1.f / 16.f);
        unsigned ub = __float_as_uint(v);
        d_Bg[(w * 9 + a) * 10 + bq] = ((u64)ub << 32) | ub;
    }
}

// y = (cf0 + cf1*CB + cf2*SB) + CT*(cf3 + cf4*CB + cf5*SB)
//                             + ST*(cf6 + cf7*CB + cf8*SB)      [8 FMA2]
__device__ __forceinline__ u64 yrowH(const u64* cf, u64 CB, u64 SB,
                                     u64 CT, u64 ST) {
    u64 t0, t1, t2;
    FMA2N(t0, cf[1], CB, cf[0]);
    FMA2(t0, cf[2], SB);
    FMA2N(t1, cf[4], CB, cf[3]);
    FMA2(t1, cf[5], SB);
    FMA2N(t2, cf[7], CB, cf[6]);
    FMA2(t2, cf[8], SB);
    FMA2(t0, CT, t1);
    FMA2(t0, ST, t2);
    return t0;
}

// ------------------------------- main kernel -------------------------------
// Block: 128 threads = 4 rows x 32 col-groups (4 patches each).
// Grid: (32 row-groups, 32 batches) = 1024 blocks; 7 CTAs/SM -> one wave.
__global__ __launch_bounds__(128, 7) void qconv_main(
    const float* __restrict__ x, float* __restrict__ out)
{
    __shared__ __align__(16) u64 sBd[4 * 9 * 10];
    const int tid = threadIdx.x;
    for (int idx = tid; idx < 360; idx += 128) sBd[idx] = d_Bg[idx];
    __syncthreads();

    const int b  = blockIdx.y;
    const int ti = tid >> 5;               // 0..3
    const int tj = tid & 31;               // 0..31
    const int i  = blockIdx.x * 4 + ti;    // output row (127 invalid)
    const int j0 = tj * 4;
    const int i0 = (i < 126) ? i : 126;

    const float* px = x + b * 16384 + i0 * 128 + j0;

    // trig for 5 columns x 2 rows
    float tv[5], bv[5];
    {
        float4 t4 = *(const float4*)px;
        float4 b4 = *(const float4*)(px + 128);
        tv[0]=t4.x; tv[1]=t4.y; tv[2]=t4.z; tv[3]=t4.w;
        bv[0]=b4.x; bv[1]=b4.y; bv[2]=b4.z; bv[3]=b4.w;
        int e = (j0 + 4 <= 127) ? 4 : 3;
        tv[4] = px[e];
        bv[4] = px[128 + e];
    }
    float ct[5], st[5], cb[5], sb[5];
#pragma unroll
    for (int c = 0; c < 5; c++) {
        __sincosf(tv[c], &st[c], &ct[c]);
        __sincosf(bv[c], &sb[c], &cb[c]);
    }

    // Packed raw-trig for column pairs q: {q, q+2}
    u64 CB[3], SB[3], CT[3], ST[3];
#pragma unroll
    for (int q = 0; q < 3; q++) {
        CB[q] = pk(cb[q], cb[q + 2]);
        SB[q] = pk(sb[q], sb[q + 2]);
        CT[q] = pk(ct[q], ct[q + 2]);
        ST[q] = pk(st[q], st[q + 2]);
    }

    const bool rowok = (i < 127);
    const bool last = (j0 + 3 >= 127);     // only patch j0+3 can be invalid
    float* ob = out + ((size_t)(b * 4) * 127 + i) * 127 + j0;

#pragma unroll 1
    for (int w = 0; w < 4; w++) {
        const u64* wp = sBd + w * 90;
        // chain0: patches (j0, j0+2): left pair 0, right pair 1
        // chain1: patches (j0+1, j0+3): left pair 1, right pair 2
        u64 sA[3], sC[3];
#pragma unroll
        for (int k0 = 0; k0 < 3; k0++) {
#pragma unroll
            for (int k2 = 0; k2 < 3; k2++) {
                const u64* rp = wp + (k0 * 3 + k2) * 10;
                u64 cf[10];
                *(ulonglong2*)(cf + 0) = *(const ulonglong2*)(rp + 0);
                *(ulonglong2*)(cf + 2) = *(const ulonglong2*)(rp + 2);
                *(ulonglong2*)(cf + 4) = *(const ulonglong2*)(rp + 4);
                *(ulonglong2*)(cf + 6) = *(const ulonglong2*)(rp + 6);
                *(ulonglong2*)(cf + 8) = *(const ulonglong2*)(rp + 8);
                u64 y0 = yrowH(cf, CB[1], SB[1], CT[1], ST[1]);
                u64 y1 = yrowH(cf, CB[2], SB[2], CT[2], ST[2]);
                if (k2 == 0) { sA[k0] = y0; sC[k0] = y1; }
                else if (k2 == 1) { FMA2(sA[k0], CB[0], y0); FMA2(sC[k0], CB[1], y1); }
                else              { FMA2(sA[k0], SB[0], y0); FMA2(sC[k0], SB[1], y1); }
            }
        }
        u64 z02 = sA[0], z13 = sC[0];
        FMA2(z02, CT[0], sA[1]);
        FMA2(z02, ST[0], sA[2]);
        FMA2(z13, CT[1], sC[1]);
        FMA2(z13, ST[1], sC[2]);

        if (rowok) {
            float* orow = ob + (size_t)w * (127 * 127);
            float lo, hi;
            upk(lo, hi, z02); orow[0] = lo; orow[2] = hi;
            upk(lo, hi, z13); orow[1] = lo;
            if (!last) orow[3] = hi;
        }
    }
}

// ------------------------------- launcher ----------------------------------
extern "C" void kernel_launch(void* const* d_in, const int* in_sizes, int n_in,
                              void* d_out, int out_size) {
    const float* x      = (const float*)d_in[0];
    const float* params = (const float*)d_in[1];
    if (n_in >= 2 && in_sizes[0] == 16) {  // robustness to input order
        params = (const float*)d_in[0];
        x      = (const float*)d_in[1];
    }
    float* out = (float*)d_out;

    qconv_precompute<<<1, 256>>>(params);
    dim3 grid(32, 32);   // 32 row-groups (4 rows) x 32 batches = 1024 blocks
    qconv_main<<<grid, 128>>>(x, out);
}

// round 14
// speedup vs baseline: 1.1366x; 1.0152x over previous
#include <cuda_runtime.h>
#include <math.h>

// ---------------------------------------------------------------------------
// QConv2D: 4-qubit circuit on every 2x2 patch of x(32,1,128,128).
// Z_w(patch) = P_L^T B_w P_R,  P = g_top (x) g_bot, g=(1,cos x,sin x).
// B_w (4 x 9 x 9) depends only on params; computed once by a tiny kernel,
// stored duplicated {c,c}. Main kernel: Horner-factored bilinear form with
// packed f32x2 FMA, 4 patches/thread, register double-buffered coefficient
// rows (hides LDS latency), PDL overlap between the two kernels.
// ---------------------------------------------------------------------------

typedef unsigned long long u64;

#define FMA2(acc, a, b) \
    asm("fma.rn.f32x2 %0, %1, %2, %0;" : "+l"(acc) : "l"(a), "l"(b))
#define FMA2N(d, a, b, c) \
    asm("fma.rn.f32x2 %0, %1, %2, %3;" : "=l"(d) : "l"(a), "l"(b), "l"(c))

__device__ __forceinline__ u64 pk(float lo, float hi) {
    u64 r; asm("mov.b64 %0, {%1, %2};" : "=l"(r) : "f"(lo), "f"(hi)); return r;
}
__device__ __forceinline__ void upk(float& lo, float& hi, u64 v) {
    asm("mov.b64 {%0, %1}, %2;" : "=f"(lo), "=f"(hi) : "l"(v));
}
__device__ __forceinline__ float2 cmulf(float2 a, float2 b) {
    return make_float2(a.x * b.x - a.y * b.y, a.x * b.y + a.y * b.x);
}

// B coefficients, duplicated {c,c}; row (w,a) = 10 u64 slots (80B):
// slots 0..8 = B_w[a][b] (b = 3*k1+k3), slot 9 = pad.
__device__ u64 d_Bg[4 * 9 * 10];

// ---------------------------- precompute kernel ----------------------------
__global__ void qconv_precompute(const float* __restrict__ params) {
    __shared__ float2 shM[2][4][2][2];
    __shared__ float2 shG[2][16][16];
    __shared__ float2 shU[16][16];
    __shared__ float  shA[4][16][16];
    const int tid = threadIdx.x;

    if (tid < 8) {  // single-qubit mats m = RZ(tz)*RX(tx)
        int l = tid >> 2, w = tid & 3;
        float tx = params[(l * 4 + w) * 2 + 0];
        float tz = params[(l * 4 + w) * 2 + 1];
        float s, c, sz, cz;
        sincosf(0.5f * tx, &s, &c);
        sincosf(0.5f * tz, &sz, &cz);
        shM[l][w][0][0] = make_float2(cz * c, -sz * c);
        shM[l][w][0][1] = make_float2(-s * sz, -s * cz);
        shM[l][w][1][0] = make_float2(s * sz, -s * cz);
        shM[l][w][1][1] = make_float2(c * cz, c * sz);
    }
    __syncthreads();

    {   // G_l = CNOTperm * (m0 (x) m1 (x) m2 (x) m3)
        int i = tid >> 4, j = tid & 15;
        int r = i;
        if (r & 1) r ^= 2;
        if (r & 2) r ^= 4;
        if (r & 4) r ^= 8;
#pragma unroll
        for (int l = 0; l < 2; l++) {
            float2 g = shM[l][0][(r >> 3) & 1][(j >> 3) & 1];
            g = cmulf(g, shM[l][1][(r >> 2) & 1][(j >> 2) & 1]);
            g = cmulf(g, shM[l][2][(r >> 1) & 1][(j >> 1) & 1]);
            g = cmulf(g, shM[l][3][r & 1][j & 1]);
            shG[l][i][j] = g;
        }
    }
    __syncthreads();

    {   // U = G1 * G0
        int i = tid >> 4, j = tid & 15;
        float2 acc = make_float2(0.f, 0.f);
#pragma unroll
        for (int m = 0; m < 16; m++) {
            float2 a = shG[1][i][m], bb = shG[0][m][j];
            acc.x += a.x * bb.x - a.y * bb.y;
            acc.y += a.x * bb.y + a.y * bb.x;
        }
        shU[i][j] = acc;
    }
    __syncthreads();

    {   // A_w[i][j] = Re( i^{popc(i)-popc(j)} sum_k d_w(k) conj(U[k,i]) U[k,j] )
        int i = tid >> 4, j = tid & 15;
        float ar[4] = {0, 0, 0, 0}, ai[4] = {0, 0, 0, 0};
#pragma unroll
        for (int k = 0; k < 16; k++) {
            float2 ui = shU[k][i], uj = shU[k][j];
            float cr = ui.x * uj.x + ui.y * uj.y;
            float ci = ui.x * uj.y - ui.y * uj.x;
#pragma unroll
            for (int w = 0; w < 4; w++) {
                float sgn = (k & (1 << (3 - w))) ? -1.f : 1.f;
                ar[w] += sgn * cr;
                ai[w] += sgn * ci;
            }
        }
        int ph = (__popc(i) - __popc(j)) & 3;
#pragma unroll
        for (int w = 0; w < 4; w++) {
            float re;
            if (ph == 0)      re =  ar[w];
            else if (ph == 1) re = -ai[w];
            else if (ph == 2) re = -ar[w];
            else              re =  ai[w];
            shA[w][i][j] = re;
        }
    }
    __syncthreads();

    // half-angle -> full-angle basis, write duplicated {v,v}
    for (int idx = tid; idx < 324; idx += 256) {
        int w = idx / 81, r = idx % 81;
        int a = r / 9, bq = r % 9;
        int k0 = a / 3, k2 = a % 3, k1 = bq / 3, k3 = bq % 3;
        int xmask = ((k0 == 2) ? 8 : 0) | ((k1 == 2) ? 4 : 0) |
                    ((k2 == 2) ? 2 : 0) | ((k3 == 2) ? 1 : 0);
        int smask = ((k0 == 1) ? 8 : 0) | ((k1 == 1) ? 4 : 0) |
                    ((k2 == 1) ? 2 : 0) | ((k3 == 1) ? 1 : 0);
        float sum = 0.f;
#pragma unroll
        for (int i = 0; i < 16; i++) {
            float sgn = (__popc(i & smask) & 1) ? -1.f : 1.f;
            sum += sgn * shA[w][i][i ^ xmask];
        }
        float v = sum * (1.f / 16.f);
        unsigned ub = __float_as_uint(v);
        d_Bg[(w * 9 + a) * 10 + bq] = ((u64)ub << 32) | ub;
    }
    // Allow PDL dependents to proceed; each thread's prior writes are ordered.
    asm volatile("griddepcontrol.launch_dependents;" ::: "memory");
}

// y = (cf0 + cf1*CB + cf2*SB) + CT*(cf3 + cf4*CB + cf5*SB)
//                             + ST*(cf6 + cf7*CB + cf8*SB)      [8 FMA2]
__device__ __forceinline__ u64 yrowH(const u64* cf, u64 CB, u64 SB,
                                     u64 CT, u64 ST) {
    u64 t0, t1, t2;
    FMA2N(t0, cf[1], CB, cf[0]);
    FMA2(t0, cf[2], SB);
    FMA2N(t1, cf[4], CB, cf[3]);
    FMA2(t1, cf[5], SB);
    FMA2N(t2, cf[7], CB, cf[6]);
    FMA2(t2, cf[8], SB);
    FMA2(t0, CT, t1);
    FMA2(t0, ST, t2);
    return t0;
}

__device__ __forceinline__ void loadrow(u64* cf, const u64* rp) {
    *(ulonglong2*)(cf + 0) = *(const ulonglong2*)(rp + 0);
    *(ulonglong2*)(cf + 2) = *(const ulonglong2*)(rp + 2);
    *(ulonglong2*)(cf + 4) = *(const ulonglong2*)(rp + 4);
    *(ulonglong2*)(cf + 6) = *(const ulonglong2*)(rp + 6);
    *(ulonglong2*)(cf + 8) = *(const ulonglong2*)(rp + 8);
}

// ------------------------------- main kernel -------------------------------
// Block: 128 threads = 4 rows x 32 col-groups (4 patches each).
// Grid: (32 row-groups, 32 batches) = 1024 blocks.
__global__ __launch_bounds__(128, 5) void qconv_main(
    const float* __restrict__ x, float* __restrict__ out)
{
    __shared__ __align__(16) u64 sBd[4 * 9 * 10];
    const int tid = threadIdx.x;

    const int b  = blockIdx.y;
    const int ti = tid >> 5;               // 0..3
    const int tj = tid & 31;               // 0..31
    const int i  = blockIdx.x * 4 + ti;    // output row (127 invalid)
    const int j0 = tj * 4;
    const int i0 = (i < 126) ? i : 126;

    const float* px = x + b * 16384 + i0 * 128 + j0;

    // ---- preamble overlaps the precompute kernel (PDL) ----
    float tv[5], bv[5];
    {
        float4 t4 = *(const float4*)px;
        float4 b4 = *(const float4*)(px + 128);
        tv[0]=t4.x; tv[1]=t4.y; tv[2]=t4.z; tv[3]=t4.w;
        bv[0]=b4.x; bv[1]=b4.y; bv[2]=b4.z; bv[3]=b4.w;
        int e = (j0 + 4 <= 127) ? 4 : 3;
        tv[4] = px[e];
        bv[4] = px[128 + e];
    }
    float ct[5], st[5], cb[5], sb[5];
#pragma unroll
    for (int c = 0; c < 5; c++) {
        __sincosf(tv[c], &st[c], &ct[c]);
        __sincosf(bv[c], &sb[c], &cb[c]);
    }

    // Packed raw-trig for column pairs q: {q, q+2}
    u64 CB[3], SB[3], CT[3], ST[3];
#pragma unroll
    for (int q = 0; q < 3; q++) {
        CB[q] = pk(cb[q], cb[q + 2]);
        SB[q] = pk(sb[q], sb[q + 2]);
        CT[q] = pk(ct[q], ct[q + 2]);
        ST[q] = pk(st[q], st[q + 2]);
    }

    // ---- wait for precompute results, then stage coefficients ----
    asm volatile("griddepcontrol.wait;" ::: "memory");
    for (int idx = tid; idx < 360; idx += 128) sBd[idx] = d_Bg[idx];
    __syncthreads();

    const bool rowok = (i < 127);
    const bool last = (j0 + 3 >= 127);     // only patch j0+3 can be invalid
    float* ob = out + ((size_t)(b * 4) * 127 + i) * 127 + j0;

#pragma unroll 1
    for (int w = 0; w < 4; w++) {
        const u64* wp = sBd + w * 90;
        // chain0: patches (j0, j0+2): left pair 0, right pair 1
        // chain1: patches (j0+1, j0+3): left pair 1, right pair 2
        u64 cf[2][10];
        loadrow(cf[0], wp);                 // row 0
        u64 sA[3], sC[3];
#pragma unroll
        for (int r = 0; r < 9; r++) {
            const int k0 = r / 3, k2 = r % 3;
            if (r < 8) loadrow(cf[(r + 1) & 1], wp + (r + 1) * 10);  // prefetch
            const u64* c = cf[r & 1];
            u64 y0 = yrowH(c, CB[1], SB[1], CT[1], ST[1]);
            u64 y1 = yrowH(c, CB[2], SB[2], CT[2], ST[2]);
            if (k2 == 0)      { sA[k0] = y0; sC[k0] = y1; }
            else if (k2 == 1) { FMA2(sA[k0], CB[0], y0); FMA2(sC[k0], CB[1], y1); }
            else              { FMA2(sA[k0], SB[0], y0); FMA2(sC[k0], SB[1], y1); }
        }
        u64 z02 = sA[0], z13 = sC[0];
        FMA2(z02, CT[0], sA[1]);
        FMA2(z02, ST[0], sA[2]);
        FMA2(z13, CT[1], sC[1]);
        FMA2(z13, ST[1], sC[2]);

        if (rowok) {
            float* orow = ob + (size_t)w * (127 * 127);
            float lo, hi;
            upk(lo, hi, z02); orow[0] = lo; orow[2] = hi;
            upk(lo, hi, z13); orow[1] = lo;
            if (!last) orow[3] = hi;
        }
    }
}

// ------------------------------- launcher ----------------------------------
extern "C" void kernel_launch(void* const* d_in, const int* in_sizes, int n_in,
                              void* d_out, int out_size) {
    const float* x      = (const float*)d_in[0];
    const float* params = (const float*)d_in[1];
    if (n_in >= 2 && in_sizes[0] == 16) {  // robustness to input order
        params = (const float*)d_in[0];
        x      = (const float*)d_in[1];
    }
    float* out = (float*)d_out;

    qconv_precompute<<<1, 256>>>(params);

    // Main kernel with programmatic dependent launch: its preamble overlaps
    // the precompute; griddepcontrol.wait gates the d_Bg read.
    dim3 grid(32, 32);
    cudaLaunchConfig_t cfg = {};
    cfg.gridDim = grid;
    cfg.blockDim = dim3(128, 1, 1);
    cfg.dynamicSmemBytes = 0;
    cfg.stream = 0;
    cudaLaunchAttribute attr[1];
    attr[0].id = cudaLaunchAttributeProgrammaticStreamSerialization;
    attr[0].val.programmaticStreamSerializationAllowed = 1;
    cfg.attrs = attr;
    cfg.numAttrs = 1;
    cudaError_t err = cudaLaunchKernelEx(&cfg, qconv_main, x, out);
    if (err != cudaSuccess) {
        // Fallback: plain launch (PDL attr unsupported) — still correct.
        qconv_main<<<grid, 128>>>(x, out);
    }
}